// round 1
// baseline (speedup 1.0000x reference)
#include <cuda_runtime.h>
#include <math_constants.h>

// MoE_27693949124969: B=4, S=4096, D=1024, E=8, top_k=2
// out[t] = sum_k  logit_k * ( x[t] @ We[e_k] + be[e_k] ),  e_k = top-2 of (x@Wg+bg)

#define T_TOKENS 16384
#define D_DIM    1024
#define E_EXP    8

// ---------------- device scratch (no allocations allowed) ----------------
__device__ int   g_cnt[2][E_EXP];
__device__ int   g_list[2][E_EXP][T_TOKENS];
__device__ float g_coef[2][E_EXP][T_TOKENS];

// ---------------- tf32 helpers ----------------
__device__ __forceinline__ float f2tf(float f) {
    unsigned u;
    asm("cvt.rna.tf32.f32 %0, %1;" : "=r"(u) : "f"(f));
    return __uint_as_float(u);
}

__device__ __forceinline__ void mma_tf32(float* d, const unsigned* a,
                                         unsigned b0, unsigned b1) {
    asm volatile(
        "mma.sync.aligned.m16n8k8.row.col.f32.tf32.tf32.f32 "
        "{%0,%1,%2,%3}, {%4,%5,%6,%7}, {%8,%9}, {%0,%1,%2,%3};\n"
        : "+f"(d[0]), "+f"(d[1]), "+f"(d[2]), "+f"(d[3])
        : "r"(a[0]), "r"(a[1]), "r"(a[2]), "r"(a[3]), "r"(b0), "r"(b1));
}

// ---------------- kernel: reset counters ----------------
__global__ void zero_kernel() {
    int t = threadIdx.x;
    if (t < 2 * E_EXP) ((int*)g_cnt)[t] = 0;
}

// ---------------- kernel: gating (full FP32 for robust top-2) ----------------
__global__ __launch_bounds__(256) void gate_kernel(
    const float* __restrict__ x,
    const float* __restrict__ Wg,   // [D, E] row-major
    const float* __restrict__ bg)   // [E]
{
    int warp = threadIdx.x >> 5;
    int lane = threadIdx.x & 31;
    int t = blockIdx.x * 8 + warp;
    if (t >= T_TOKENS) return;

    const float4* xr  = (const float4*)(x + (size_t)t * D_DIM);
    const float4* wg4 = (const float4*)Wg;

    float acc[8] = {0.f,0.f,0.f,0.f,0.f,0.f,0.f,0.f};
    #pragma unroll
    for (int i = 0; i < 8; i++) {
        int d0 = i * 128 + lane * 4;
        float4 xv = xr[d0 >> 2];
        float xs[4] = {xv.x, xv.y, xv.z, xv.w};
        #pragma unroll
        for (int j = 0; j < 4; j++) {
            int d = d0 + j;
            float4 w0 = wg4[d * 2];
            float4 w1 = wg4[d * 2 + 1];
            acc[0] += xs[j] * w0.x; acc[1] += xs[j] * w0.y;
            acc[2] += xs[j] * w0.z; acc[3] += xs[j] * w0.w;
            acc[4] += xs[j] * w1.x; acc[5] += xs[j] * w1.y;
            acc[6] += xs[j] * w1.z; acc[7] += xs[j] * w1.w;
        }
    }
    #pragma unroll
    for (int e = 0; e < 8; e++) {
        #pragma unroll
        for (int off = 16; off; off >>= 1)
            acc[e] += __shfl_xor_sync(0xFFFFFFFFu, acc[e], off);
    }

    if (lane == 0) {
        float l[8];
        #pragma unroll
        for (int e = 0; e < 8; e++) l[e] = acc[e] + bg[e];
        // top-1 (strict > keeps lowest index on tie, matching jax.lax.top_k)
        int e0 = 0; float v0 = l[0];
        #pragma unroll
        for (int e = 1; e < 8; e++) if (l[e] > v0) { v0 = l[e]; e0 = e; }
        int e1 = -1; float v1 = -CUDART_INF_F;
        #pragma unroll
        for (int e = 0; e < 8; e++)
            if (e != e0 && l[e] > v1) { v1 = l[e]; e1 = e; }

        int p0 = atomicAdd(&g_cnt[0][e0], 1);
        g_list[0][e0][p0] = t;  g_coef[0][e0][p0] = v0;
        int p1 = atomicAdd(&g_cnt[1][e1], 1);
        g_list[1][e1][p1] = t;  g_coef[1][e1][p1] = v1;
    }
}

// ---------------- kernel: grouped GEMM per (expert, slot) ----------------
// Tile: 128 rows (gathered tokens) x 128 cols, K=1024 in chunks of 32.
// slot 0: out = coef*(xW + be).  slot 1: out += coef*(xW + be).
__global__ __launch_bounds__(256) void moe_gemm_kernel(
    const float* __restrict__ x,
    const float* __restrict__ We,   // [E, D, D]
    const float* __restrict__ be,   // [E, D]
    float* __restrict__ out,
    int slot)
{
    __shared__ __align__(16) float As[128][36];   // stride 36: conflict-free A frags
    __shared__ __align__(16) float Bs[32][136];   // stride 136: conflict-free B frags
    __shared__ int   s_tok[128];
    __shared__ float s_cf[128];
    __shared__ float s_be[128];

    const int e  = blockIdx.z;
    const int mt = blockIdx.y;
    const int nt = blockIdx.x;

    const int nrows = g_cnt[slot][e];
    const int row0  = mt * 128;
    if (row0 >= nrows) return;
    const int mrows = min(128, nrows - row0);

    const int tid = threadIdx.x;
    if (tid < 128) {
        int tok = 0; float cf = 0.f;
        if (tid < mrows) {
            tok = g_list[slot][e][row0 + tid];
            cf  = g_coef[slot][e][row0 + tid];
        }
        s_tok[tid] = tok;
        s_cf[tid]  = cf;
        s_be[tid]  = be[e * D_DIM + nt * 128 + tid];
    }
    __syncthreads();

    const int lane = tid & 31, warp = tid >> 5;
    const int wm = warp >> 2, wn = warp & 3;    // 2x4 warp grid, 64x32 warp tile
    const int qr = lane >> 2, qc = lane & 3;

    float acc[4][4][4];
    #pragma unroll
    for (int i = 0; i < 4; i++)
        #pragma unroll
        for (int j = 0; j < 4; j++)
            #pragma unroll
            for (int c = 0; c < 4; c++) acc[i][j][c] = 0.f;

    const float* Wbase = We + (size_t)e * D_DIM * D_DIM + nt * 128;

    for (int kc = 0; kc < 32; kc++) {
        // ---- stage A: gather 128 token rows x 32 k-cols (f32 -> tf32) ----
        #pragma unroll
        for (int i = 0; i < 4; i++) {
            int f   = tid + i * 256;         // float4 index, 1024 total
            int row = f >> 3, c4 = f & 7;
            const float4* p =
                (const float4*)(x + (size_t)s_tok[row] * D_DIM + kc * 32) + c4;
            float4 v = *p;
            v.x = f2tf(v.x); v.y = f2tf(v.y); v.z = f2tf(v.z); v.w = f2tf(v.w);
            *((float4*)&As[row][c4 * 4]) = v;
        }
        // ---- stage B: 32 k-rows x 128 n-cols of We[e] (f32 -> tf32) ----
        #pragma unroll
        for (int i = 0; i < 4; i++) {
            int f  = tid + i * 256;
            int kr = f >> 5, c4 = f & 31;
            const float4* p =
                (const float4*)(Wbase + (size_t)(kc * 32 + kr) * D_DIM) + c4;
            float4 v = *p;
            v.x = f2tf(v.x); v.y = f2tf(v.y); v.z = f2tf(v.z); v.w = f2tf(v.w);
            *((float4*)&Bs[kr][c4 * 4]) = v;
        }
        __syncthreads();

        #pragma unroll
        for (int ks = 0; ks < 4; ks++) {
            const int kb = ks * 8;
            unsigned a[4][4], b[4][2];
            #pragma unroll
            for (int fm = 0; fm < 4; fm++) {
                int rb = wm * 64 + fm * 16;
                a[fm][0] = __float_as_uint(As[rb + qr    ][kb + qc    ]);
                a[fm][1] = __float_as_uint(As[rb + qr + 8][kb + qc    ]);
                a[fm][2] = __float_as_uint(As[rb + qr    ][kb + qc + 4]);
                a[fm][3] = __float_as_uint(As[rb + qr + 8][kb + qc + 4]);
            }
            #pragma unroll
            for (int fn = 0; fn < 4; fn++) {
                int cb = wn * 32 + fn * 8;
                b[fn][0] = __float_as_uint(Bs[kb + qc    ][cb + qr]);
                b[fn][1] = __float_as_uint(Bs[kb + qc + 4][cb + qr]);
            }
            #pragma unroll
            for (int fm = 0; fm < 4; fm++)
                #pragma unroll
                for (int fn = 0; fn < 4; fn++)
                    mma_tf32(acc[fm][fn], a[fm], b[fn][0], b[fn][1]);
        }
        __syncthreads();
    }

    // ---- epilogue: scale by coef, add bias, scatter to tokens ----
    #pragma unroll
    for (int fm = 0; fm < 4; fm++) {
        int rb = wm * 64 + fm * 16 + qr;
        #pragma unroll
        for (int fn = 0; fn < 4; fn++) {
            int lc = wn * 32 + fn * 8 + qc * 2;
            float be0 = s_be[lc], be1 = s_be[lc + 1];
            #pragma unroll
            for (int h = 0; h < 2; h++) {
                int r = rb + h * 8;
                if (r < mrows) {
                    int   tok = s_tok[r];
                    float cf  = s_cf[r];
                    float2* po =
                        (float2*)(out + (size_t)tok * D_DIM + nt * 128 + lc);
                    float2 v;
                    v.x = cf * (acc[fm][fn][h * 2 + 0] + be0);
                    v.y = cf * (acc[fm][fn][h * 2 + 1] + be1);
                    if (slot == 0) {
                        *po = v;
                    } else {
                        float2 o = *po;
                        o.x += v.x; o.y += v.y;
                        *po = o;
                    }
                }
            }
        }
    }
}

// ---------------- launch ----------------
extern "C" void kernel_launch(void* const* d_in, const int* in_sizes, int n_in,
                              void* d_out, int out_size)
{
    const float* x  = (const float*)d_in[0];
    // d_in[1] = router_mask (unused by reference)
    const float* We = (const float*)d_in[2];
    const float* be = (const float*)d_in[3];
    const float* Wg = (const float*)d_in[4];
    const float* bg = (const float*)d_in[5];
    float* out = (float*)d_out;

    zero_kernel<<<1, 32>>>();
    gate_kernel<<<T_TOKENS / 8, 256>>>(x, Wg, bg);

    dim3 grid(8 /*ntiles*/, 128 /*mtiles max*/, E_EXP);
    moe_gemm_kernel<<<grid, 256>>>(x, We, be, out, 0);  // writes '='
    moe_gemm_kernel<<<grid, 256>>>(x, We, be, out, 1);  // writes '+='
}

// round 2
// speedup vs baseline: 1.6528x; 1.6528x over previous
#include <cuda_runtime.h>
#include <math_constants.h>

// MoE_27693949124969: B=4, S=4096, D=1024, E=8, top_k=2
// out[t] = sum_k logit_k * ( x[t] @ We[e_k] + be[e_k] ),  e_k = top-2 of (x@Wg+bg)

#define T_TOKENS 16384
#define D_DIM    1024
#define E_EXP    8
#define KT       32          // K chunks of 32 (32*32 = 1024)
#define STAGES   3

// ---------------- device scratch (no dynamic allocation allowed) ----------------
__device__ int   g_cnt[2][E_EXP];
__device__ int   g_list[2][E_EXP][T_TOKENS];
__device__ float g_coef[2][E_EXP][T_TOKENS];
__device__ float g_xcvt[(size_t)T_TOKENS * D_DIM];          // tf32-rounded x  (64 MB)
__device__ float g_Wcvt[(size_t)E_EXP * D_DIM * D_DIM];     // tf32-rounded We (32 MB)

// ---------------- helpers ----------------
__device__ __forceinline__ float f2tf(float f) {
    unsigned u;
    asm("cvt.rna.tf32.f32 %0, %1;" : "=r"(u) : "f"(f));
    return __uint_as_float(u);
}

__device__ __forceinline__ void mma_tf32(float* d, const unsigned* a,
                                         unsigned b0, unsigned b1) {
    asm volatile(
        "mma.sync.aligned.m16n8k8.row.col.f32.tf32.tf32.f32 "
        "{%0,%1,%2,%3}, {%4,%5,%6,%7}, {%8,%9}, {%0,%1,%2,%3};\n"
        : "+f"(d[0]), "+f"(d[1]), "+f"(d[2]), "+f"(d[3])
        : "r"(a[0]), "r"(a[1]), "r"(a[2]), "r"(a[3]), "r"(b0), "r"(b1));
}

__device__ __forceinline__ void cp16(float* s, const float* g) {
    unsigned sa = (unsigned)__cvta_generic_to_shared(s);
    asm volatile("cp.async.cg.shared.global [%0], [%1], 16;\n" :: "r"(sa), "l"(g));
}
__device__ __forceinline__ void cp_commit() {
    asm volatile("cp.async.commit_group;\n");
}
__device__ __forceinline__ void cp_wait1() {
    asm volatile("cp.async.wait_group 1;\n");
}

// ---------------- kernel: reset counters ----------------
__global__ void zero_kernel() {
    int t = threadIdx.x;
    if (t < 2 * E_EXP) ((int*)g_cnt)[t] = 0;
}

// ---------------- kernel: round We -> tf32 once ----------------
__global__ __launch_bounds__(256) void wcvt_kernel(const float* __restrict__ We) {
    size_t i = (size_t)blockIdx.x * 256 + threadIdx.x;   // float4 index
    float4 v = ((const float4*)We)[i];
    v.x = f2tf(v.x); v.y = f2tf(v.y); v.z = f2tf(v.z); v.w = f2tf(v.w);
    ((float4*)g_Wcvt)[i] = v;
}

// ---------------- kernel: gating (fp32) + write tf32-rounded x ----------------
__global__ __launch_bounds__(256) void gate_kernel(
    const float* __restrict__ x,
    const float* __restrict__ Wg,   // [D, E]
    const float* __restrict__ bg)   // [E]
{
    int warp = threadIdx.x >> 5;
    int lane = threadIdx.x & 31;
    int t = blockIdx.x * 8 + warp;
    if (t >= T_TOKENS) return;

    const float4* xr  = (const float4*)(x + (size_t)t * D_DIM);
    float4*       xc  = (float4*)(g_xcvt + (size_t)t * D_DIM);
    const float4* wg4 = (const float4*)Wg;

    float acc[8] = {0.f,0.f,0.f,0.f,0.f,0.f,0.f,0.f};
    #pragma unroll
    for (int i = 0; i < 8; i++) {
        int d0 = i * 128 + lane * 4;
        float4 xv = xr[i * 32 + lane];
        // side-product: rounded copy of x for the tf32 GEMM
        float4 cv;
        cv.x = f2tf(xv.x); cv.y = f2tf(xv.y); cv.z = f2tf(xv.z); cv.w = f2tf(xv.w);
        xc[i * 32 + lane] = cv;

        float xs[4] = {xv.x, xv.y, xv.z, xv.w};
        #pragma unroll
        for (int j = 0; j < 4; j++) {
            int d = d0 + j;
            float4 w0 = wg4[d * 2];
            float4 w1 = wg4[d * 2 + 1];
            acc[0] += xs[j] * w0.x; acc[1] += xs[j] * w0.y;
            acc[2] += xs[j] * w0.z; acc[3] += xs[j] * w0.w;
            acc[4] += xs[j] * w1.x; acc[5] += xs[j] * w1.y;
            acc[6] += xs[j] * w1.z; acc[7] += xs[j] * w1.w;
        }
    }
    #pragma unroll
    for (int e = 0; e < 8; e++) {
        #pragma unroll
        for (int off = 16; off; off >>= 1)
            acc[e] += __shfl_xor_sync(0xFFFFFFFFu, acc[e], off);
    }

    if (lane == 0) {
        float l[8];
        #pragma unroll
        for (int e = 0; e < 8; e++) l[e] = acc[e] + bg[e];
        int e0 = 0; float v0 = l[0];
        #pragma unroll
        for (int e = 1; e < 8; e++) if (l[e] > v0) { v0 = l[e]; e0 = e; }
        int e1 = -1; float v1 = -CUDART_INF_F;
        #pragma unroll
        for (int e = 0; e < 8; e++)
            if (e != e0 && l[e] > v1) { v1 = l[e]; e1 = e; }

        int p0 = atomicAdd(&g_cnt[0][e0], 1);
        g_list[0][e0][p0] = t;  g_coef[0][e0][p0] = v0;
        int p1 = atomicAdd(&g_cnt[1][e1], 1);
        g_list[1][e1][p1] = t;  g_coef[1][e1][p1] = v1;
    }
}

// ---------------- kernel: grouped GEMM, cp.async 3-stage pipeline ----------------
// Tile 128x128, K chunks of 32. Inputs pre-rounded to tf32 (g_xcvt / g_Wcvt).
// slot 0: out = coef*(xW + be).  slot 1: out += coef*(xW + be).
#define AS_STRIDE 36
#define BS_STRIDE 136
#define AS_FLOATS (128 * AS_STRIDE)
#define BS_FLOATS (32 * BS_STRIDE)
#define SMEM_FLOATS (STAGES * (AS_FLOATS + BS_FLOATS))

__global__ __launch_bounds__(256, 2) void moe_gemm_kernel(
    const float* __restrict__ be,   // [E, D]
    float* __restrict__ out,
    int slot)
{
    extern __shared__ float smem[];
    float* As = smem;                            // [STAGES][128][36]
    float* Bs = smem + STAGES * AS_FLOATS;       // [STAGES][32][136]

    __shared__ int   s_tok[128];
    __shared__ float s_cf[128];
    __shared__ float s_be[128];

    const int e  = blockIdx.z;
    const int mt = blockIdx.y;
    const int nt = blockIdx.x;

    const int nrows = g_cnt[slot][e];
    const int row0  = mt * 128;
    if (row0 >= nrows) return;
    const int mrows = min(128, nrows - row0);

    const int tid = threadIdx.x;
    if (tid < 128) {
        int tok = 0; float cf = 0.f;
        if (tid < mrows) {
            tok = g_list[slot][e][row0 + tid];
            cf  = g_coef[slot][e][row0 + tid];
        }
        s_tok[tid] = tok;
        s_cf[tid]  = cf;
        s_be[tid]  = be[e * D_DIM + nt * 128 + tid];
    }
    __syncthreads();

    // per-thread fixed gather addresses (only the k-offset advances)
    const float* a_g[4];
    int a_soff[4];
    #pragma unroll
    for (int i = 0; i < 4; i++) {
        int f   = tid + i * 256;           // 1024 float4 slots of the A tile
        int row = f >> 3, c4 = f & 7;
        a_g[i]    = g_xcvt + (size_t)s_tok[row] * D_DIM + c4 * 4;
        a_soff[i] = row * AS_STRIDE + c4 * 4;
    }
    const float* Wbase = g_Wcvt + (size_t)e * D_DIM * D_DIM + nt * 128;
    const float* b_g[4];
    int b_soff[4];
    #pragma unroll
    for (int i = 0; i < 4; i++) {
        int f  = tid + i * 256;
        int kr = f >> 5, c4 = f & 31;
        b_g[i]    = Wbase + (size_t)kr * D_DIM + c4 * 4;
        b_soff[i] = kr * BS_STRIDE + c4 * 4;
    }

    // prologue: prefetch stages 0,1
    #pragma unroll
    for (int s = 0; s < 2; s++) {
        float* Ast = As + s * AS_FLOATS;
        float* Bst = Bs + s * BS_FLOATS;
        #pragma unroll
        for (int i = 0; i < 4; i++) cp16(Ast + a_soff[i], a_g[i] + s * 32);
        #pragma unroll
        for (int i = 0; i < 4; i++) cp16(Bst + b_soff[i], b_g[i] + (size_t)s * 32 * D_DIM);
        cp_commit();
    }

    const int lane = tid & 31, warp = tid >> 5;
    const int wm = warp >> 2, wn = warp & 3;    // 2x4 warp grid, 64x32 warp tile
    const int qr = lane >> 2, qc = lane & 3;

    float acc[4][4][4];
    #pragma unroll
    for (int i = 0; i < 4; i++)
        #pragma unroll
        for (int j = 0; j < 4; j++)
            #pragma unroll
            for (int c = 0; c < 4; c++) acc[i][j][c] = 0.f;

    for (int kc = 0; kc < KT; kc++) {
        const int st = kc % STAGES;
        cp_wait1();            // chunk kc resident
        __syncthreads();       // also guards reuse of stage (kc+2)%STAGES

        if (kc + 2 < KT) {
            const int sn = (kc + 2) % STAGES;
            float* Ast = As + sn * AS_FLOATS;
            float* Bst = Bs + sn * BS_FLOATS;
            #pragma unroll
            for (int i = 0; i < 4; i++) cp16(Ast + a_soff[i], a_g[i] + (kc + 2) * 32);
            #pragma unroll
            for (int i = 0; i < 4; i++)
                cp16(Bst + b_soff[i], b_g[i] + (size_t)(kc + 2) * 32 * D_DIM);
        }
        cp_commit();           // keep one group per iteration (possibly empty)

        const float* Ast = As + st * AS_FLOATS;
        const float* Bst = Bs + st * BS_FLOATS;
        #pragma unroll
        for (int ks = 0; ks < 4; ks++) {
            const int kb = ks * 8;
            unsigned a[4][4], b[4][2];
            #pragma unroll
            for (int fm = 0; fm < 4; fm++) {
                int rb = wm * 64 + fm * 16;
                a[fm][0] = __float_as_uint(Ast[(rb + qr    ) * AS_STRIDE + kb + qc    ]);
                a[fm][1] = __float_as_uint(Ast[(rb + qr + 8) * AS_STRIDE + kb + qc    ]);
                a[fm][2] = __float_as_uint(Ast[(rb + qr    ) * AS_STRIDE + kb + qc + 4]);
                a[fm][3] = __float_as_uint(Ast[(rb + qr + 8) * AS_STRIDE + kb + qc + 4]);
            }
            #pragma unroll
            for (int fn = 0; fn < 4; fn++) {
                int cb = wn * 32 + fn * 8;
                b[fn][0] = __float_as_uint(Bst[(kb + qc    ) * BS_STRIDE + cb + qr]);
                b[fn][1] = __float_as_uint(Bst[(kb + qc + 4) * BS_STRIDE + cb + qr]);
            }
            #pragma unroll
            for (int fm = 0; fm < 4; fm++)
                #pragma unroll
                for (int fn = 0; fn < 4; fn++)
                    mma_tf32(acc[fm][fn], a[fm], b[fn][0], b[fn][1]);
        }
    }

    // ---- epilogue: scale by coef, add bias, scatter to tokens ----
    #pragma unroll
    for (int fm = 0; fm < 4; fm++) {
        int rb = wm * 64 + fm * 16 + qr;
        #pragma unroll
        for (int fn = 0; fn < 4; fn++) {
            int lc = wn * 32 + fn * 8 + qc * 2;
            float be0 = s_be[lc], be1 = s_be[lc + 1];
            #pragma unroll
            for (int h = 0; h < 2; h++) {
                int r = rb + h * 8;
                if (r < mrows) {
                    int   tok = s_tok[r];
                    float cf  = s_cf[r];
                    float2* po =
                        (float2*)(out + (size_t)tok * D_DIM + nt * 128 + lc);
                    float2 v;
                    v.x = cf * (acc[fm][fn][h * 2 + 0] + be0);
                    v.y = cf * (acc[fm][fn][h * 2 + 1] + be1);
                    if (slot == 0) {
                        *po = v;
                    } else {
                        float2 o = *po;
                        o.x += v.x; o.y += v.y;
                        *po = o;
                    }
                }
            }
        }
    }
}

// ---------------- launch ----------------
extern "C" void kernel_launch(void* const* d_in, const int* in_sizes, int n_in,
                              void* d_out, int out_size)
{
    const float* x  = (const float*)d_in[0];
    // d_in[1] = router_mask (unused by reference)
    const float* We = (const float*)d_in[2];
    const float* be = (const float*)d_in[3];
    const float* Wg = (const float*)d_in[4];
    const float* bg = (const float*)d_in[5];
    float* out = (float*)d_out;

    const int smem_bytes = SMEM_FLOATS * sizeof(float);   // 107,520 B
    cudaFuncSetAttribute(moe_gemm_kernel,
                         cudaFuncAttributeMaxDynamicSharedMemorySize, smem_bytes);

    zero_kernel<<<1, 32>>>();
    gate_kernel<<<T_TOKENS / 8, 256>>>(x, Wg, bg);
    wcvt_kernel<<<(E_EXP * D_DIM * D_DIM / 4) / 256, 256>>>(We);

    dim3 grid(8 /*ntiles*/, 128 /*mtiles max*/, E_EXP);
    moe_gemm_kernel<<<grid, 256, smem_bytes>>>(be, out, 0);  // writes '='
    moe_gemm_kernel<<<grid, 256, smem_bytes>>>(be, out, 1);  // writes '+='
}

// round 3
// speedup vs baseline: 1.7233x; 1.0427x over previous
#include <cuda_runtime.h>
#include <math_constants.h>

// MoE_27693949124969: B=4, S=4096, D=1024, E=8, top_k=2
// out[t] = sum_k logit_k * ( x[t] @ We[e_k] + be[e_k] ),  e_k = top-2 of (x@Wg+bg)

#define T_TOKENS 16384
#define D_DIM    1024
#define E_EXP    8
#define KT       32          // K chunks of 32 (32*32 = 1024)
#define STAGES   3
#define TS       36          // smem row stride (floats) for both 128x32 tiles

// ---------------- device scratch (no dynamic allocation allowed) ----------------
__device__ int   g_cnt[2][E_EXP];
__device__ int   g_list[2][E_EXP][T_TOKENS];
__device__ float g_coef[2][E_EXP][T_TOKENS];
__device__ float g_xcvt[(size_t)T_TOKENS * D_DIM];          // tf32-rounded x       (64 MB)
__device__ float g_Wt[(size_t)E_EXP * D_DIM * D_DIM];       // tf32-rounded We^T    (32 MB)

// ---------------- helpers ----------------
__device__ __forceinline__ float f2tf(float f) {
    unsigned u;
    asm("cvt.rna.tf32.f32 %0, %1;" : "=r"(u) : "f"(f));
    return __uint_as_float(u);
}

__device__ __forceinline__ void mma_tf32(float* d, const unsigned* a,
                                         unsigned b0, unsigned b1) {
    asm volatile(
        "mma.sync.aligned.m16n8k8.row.col.f32.tf32.tf32.f32 "
        "{%0,%1,%2,%3}, {%4,%5,%6,%7}, {%8,%9}, {%0,%1,%2,%3};\n"
        : "+f"(d[0]), "+f"(d[1]), "+f"(d[2]), "+f"(d[3])
        : "r"(a[0]), "r"(a[1]), "r"(a[2]), "r"(a[3]), "r"(b0), "r"(b1));
}

__device__ __forceinline__ void ldsm4(unsigned* r, unsigned addr) {
    asm volatile("ldmatrix.sync.aligned.m8n8.x4.shared.b16 {%0,%1,%2,%3}, [%4];"
                 : "=r"(r[0]), "=r"(r[1]), "=r"(r[2]), "=r"(r[3]) : "r"(addr));
}

__device__ __forceinline__ void cp16(float* s, const float* g) {
    unsigned sa = (unsigned)__cvta_generic_to_shared(s);
    asm volatile("cp.async.cg.shared.global [%0], [%1], 16;\n" :: "r"(sa), "l"(g));
}
__device__ __forceinline__ void cp_commit() {
    asm volatile("cp.async.commit_group;\n");
}
__device__ __forceinline__ void cp_wait1() {
    asm volatile("cp.async.wait_group 1;\n");
}

// ---------------- kernel: reset counters ----------------
__global__ void zero_kernel() {
    int t = threadIdx.x;
    if (t < 2 * E_EXP) ((int*)g_cnt)[t] = 0;
}

// ---------------- kernel: prep = gating (+xcvt)  ||  We transpose+round ----------------
// blocks [0, 2048):     gating, 8 tokens per block (warp-per-token)
// blocks [2048, 10240): 32x32 tiled transpose of We into g_Wt (tf32-rounded)
__global__ __launch_bounds__(256) void prep_kernel(
    const float* __restrict__ x,
    const float* __restrict__ We,   // [E, D, D]  (k-major rows, n contiguous)
    const float* __restrict__ Wg,   // [D, E]
    const float* __restrict__ bg)   // [E]
{
    __shared__ float ts[32][33];

    if (blockIdx.x >= 2048) {
        // -------- transpose + round We --------
        int b  = blockIdx.x - 2048;          // 8192 blocks = 8 experts x 1024 tiles
        int e  = b >> 10;
        int t  = b & 1023;
        int k0 = (t >> 5) * 32;
        int n0 = (t & 31) * 32;
        int tx = threadIdx.x & 31;
        int ty = threadIdx.x >> 5;           // 0..7

        const float* src = We + (size_t)e * D_DIM * D_DIM;
        float*       dst = g_Wt + (size_t)e * D_DIM * D_DIM;

        #pragma unroll
        for (int i = 0; i < 4; i++) {
            int k = k0 + ty + i * 8;
            ts[ty + i * 8][tx] = f2tf(src[(size_t)k * D_DIM + n0 + tx]);
        }
        __syncthreads();
        #pragma unroll
        for (int i = 0; i < 4; i++) {
            int n = n0 + ty + i * 8;
            dst[(size_t)n * D_DIM + k0 + tx] = ts[tx][ty + i * 8];
        }
        return;
    }

    // -------- gating --------
    int warp = threadIdx.x >> 5;
    int lane = threadIdx.x & 31;
    int t = blockIdx.x * 8 + warp;

    const float4* xr  = (const float4*)(x + (size_t)t * D_DIM);
    float4*       xc  = (float4*)(g_xcvt + (size_t)t * D_DIM);
    const float4* wg4 = (const float4*)Wg;

    float acc[8] = {0.f,0.f,0.f,0.f,0.f,0.f,0.f,0.f};
    #pragma unroll
    for (int i = 0; i < 8; i++) {
        int d0 = i * 128 + lane * 4;
        float4 xv = xr[i * 32 + lane];
        float4 cv;
        cv.x = f2tf(xv.x); cv.y = f2tf(xv.y); cv.z = f2tf(xv.z); cv.w = f2tf(xv.w);
        xc[i * 32 + lane] = cv;

        float xs[4] = {xv.x, xv.y, xv.z, xv.w};
        #pragma unroll
        for (int j = 0; j < 4; j++) {
            int d = d0 + j;
            float4 w0 = wg4[d * 2];
            float4 w1 = wg4[d * 2 + 1];
            acc[0] += xs[j] * w0.x; acc[1] += xs[j] * w0.y;
            acc[2] += xs[j] * w0.z; acc[3] += xs[j] * w0.w;
            acc[4] += xs[j] * w1.x; acc[5] += xs[j] * w1.y;
            acc[6] += xs[j] * w1.z; acc[7] += xs[j] * w1.w;
        }
    }
    #pragma unroll
    for (int e = 0; e < 8; e++) {
        #pragma unroll
        for (int off = 16; off; off >>= 1)
            acc[e] += __shfl_xor_sync(0xFFFFFFFFu, acc[e], off);
    }

    if (lane == 0) {
        float l[8];
        #pragma unroll
        for (int e = 0; e < 8; e++) l[e] = acc[e] + bg[e];
        int e0 = 0; float v0 = l[0];
        #pragma unroll
        for (int e = 1; e < 8; e++) if (l[e] > v0) { v0 = l[e]; e0 = e; }
        int e1 = -1; float v1 = -CUDART_INF_F;
        #pragma unroll
        for (int e = 0; e < 8; e++)
            if (e != e0 && l[e] > v1) { v1 = l[e]; e1 = e; }

        int p0 = atomicAdd(&g_cnt[0][e0], 1);
        g_list[0][e0][p0] = t;  g_coef[0][e0][p0] = v0;
        int p1 = atomicAdd(&g_cnt[1][e1], 1);
        g_list[1][e1][p1] = t;  g_coef[1][e1][p1] = v1;
    }
}

// ---------------- kernel: grouped GEMM, cp.async pipeline + ldmatrix ----------------
// Tile 128x128, K chunks of 32. A = gathered tokens (g_xcvt), B = g_Wt rows (k-contiguous).
// slot 0: out = coef*(xW + be).  slot 1: out += coef*(xW + be).
#define TILE_FLOATS (128 * TS)                  // 4608 floats per 128x32 tile
#define STG_FLOATS  (2 * TILE_FLOATS)           // A tile + B tile per stage
#define SMEM_FLOATS (STAGES * STG_FLOATS)       // 27648 floats = 110592 B
#define STG_BYTES   (STG_FLOATS * 4)
#define BOFF_BYTES  (TILE_FLOATS * 4)

__global__ __launch_bounds__(256, 2) void moe_gemm_kernel(
    const float* __restrict__ be,   // [E, D]
    float* __restrict__ out,
    int slot)
{
    extern __shared__ float smem[];

    __shared__ int   s_tok[128];
    __shared__ float s_cf[128];
    __shared__ float s_be[128];

    const int e  = blockIdx.z;
    const int mt = blockIdx.y;
    const int nt = blockIdx.x;

    const int nrows = g_cnt[slot][e];
    const int row0  = mt * 128;
    if (row0 >= nrows) return;
    const int mrows = min(128, nrows - row0);

    const int tid = threadIdx.x;
    if (tid < 128) {
        int tok = 0; float cf = 0.f;
        if (tid < mrows) {
            tok = g_list[slot][e][row0 + tid];
            cf  = g_coef[slot][e][row0 + tid];
        }
        s_tok[tid] = tok;
        s_cf[tid]  = cf;
        s_be[tid]  = be[e * D_DIM + nt * 128 + tid];
    }
    __syncthreads();

    // per-thread gather addresses: both tiles are 128 rows x 32 k-floats
    const float* a_g[4];
    const float* b_g[4];
    int soff[4];
    #pragma unroll
    for (int i = 0; i < 4; i++) {
        int f   = tid + i * 256;           // 1024 float4 slots per tile
        int row = f >> 3, c4 = f & 7;
        a_g[i]  = g_xcvt + (size_t)s_tok[row] * D_DIM + c4 * 4;
        b_g[i]  = g_Wt + ((size_t)e * D_DIM + nt * 128 + row) * D_DIM + c4 * 4;
        soff[i] = row * TS + c4 * 4;
    }

    // prologue: prefetch stages 0,1
    #pragma unroll
    for (int s = 0; s < 2; s++) {
        float* Ast = smem + s * STG_FLOATS;
        float* Bst = Ast + TILE_FLOATS;
        #pragma unroll
        for (int i = 0; i < 4; i++) cp16(Ast + soff[i], a_g[i] + s * 32);
        #pragma unroll
        for (int i = 0; i < 4; i++) cp16(Bst + soff[i], b_g[i] + s * 32);
        cp_commit();
    }

    const int lane = tid & 31, warp = tid >> 5;
    const int wm = warp >> 2, wn = warp & 3;    // 2x4 warp grid, 64x32 warp tile
    const int qr = lane >> 2, qc = lane & 3;
    const int g  = lane >> 3, r  = lane & 7;

    // ldmatrix per-lane addresses (bytes, within stage)
    const unsigned smem_u = (unsigned)__cvta_generic_to_shared(smem);
    const unsigned a_lds = ((wm * 64 + (g & 1) * 8 + r) * TS + (g >> 1) * 4) * 4;
    const unsigned b_lds = ((wn * 32 + (g >> 1) * 8 + r) * TS + (g & 1) * 4) * 4;

    float acc[4][4][4];
    #pragma unroll
    for (int i = 0; i < 4; i++)
        #pragma unroll
        for (int j = 0; j < 4; j++)
            #pragma unroll
            for (int c = 0; c < 4; c++) acc[i][j][c] = 0.f;

    for (int kc = 0; kc < KT; kc++) {
        const int st = kc % STAGES;
        cp_wait1();            // chunk kc resident
        __syncthreads();       // also guards reuse of stage (kc+2)%STAGES

        if (kc + 2 < KT) {
            const int sn = (kc + 2) % STAGES;
            float* Ast = smem + sn * STG_FLOATS;
            float* Bst = Ast + TILE_FLOATS;
            #pragma unroll
            for (int i = 0; i < 4; i++) cp16(Ast + soff[i], a_g[i] + (kc + 2) * 32);
            #pragma unroll
            for (int i = 0; i < 4; i++) cp16(Bst + soff[i], b_g[i] + (kc + 2) * 32);
        }
        cp_commit();           // one group per iteration (possibly empty)

        const unsigned sA = smem_u + st * STG_BYTES + a_lds;
        const unsigned sB = smem_u + st * STG_BYTES + BOFF_BYTES + b_lds;
        #pragma unroll
        for (int ks = 0; ks < 4; ks++) {
            unsigned a[4][4], bb[2][4];
            #pragma unroll
            for (int fm = 0; fm < 4; fm++)
                ldsm4(a[fm], sA + fm * (16 * TS * 4) + ks * 32);
            #pragma unroll
            for (int fnp = 0; fnp < 2; fnp++)
                ldsm4(bb[fnp], sB + fnp * (16 * TS * 4) + ks * 32);
            #pragma unroll
            for (int fm = 0; fm < 4; fm++)
                #pragma unroll
                for (int fn = 0; fn < 4; fn++)
                    mma_tf32(acc[fm][fn], a[fm],
                             bb[fn >> 1][(fn & 1) * 2], bb[fn >> 1][(fn & 1) * 2 + 1]);
        }
    }

    // ---- epilogue: scale by coef, add bias, scatter to tokens ----
    #pragma unroll
    for (int fm = 0; fm < 4; fm++) {
        int rb = wm * 64 + fm * 16 + qr;
        #pragma unroll
        for (int fn = 0; fn < 4; fn++) {
            int lc = wn * 32 + fn * 8 + qc * 2;
            float be0 = s_be[lc], be1 = s_be[lc + 1];
            #pragma unroll
            for (int h = 0; h < 2; h++) {
                int rr = rb + h * 8;
                if (rr < mrows) {
                    int   tok = s_tok[rr];
                    float cf  = s_cf[rr];
                    float2* po =
                        (float2*)(out + (size_t)tok * D_DIM + nt * 128 + lc);
                    float2 v;
                    v.x = cf * (acc[fm][fn][h * 2 + 0] + be0);
                    v.y = cf * (acc[fm][fn][h * 2 + 1] + be1);
                    if (slot == 0) {
                        *po = v;
                    } else {
                        float2 o = *po;
                        o.x += v.x; o.y += v.y;
                        *po = o;
                    }
                }
            }
        }
    }
}

// ---------------- launch ----------------
extern "C" void kernel_launch(void* const* d_in, const int* in_sizes, int n_in,
                              void* d_out, int out_size)
{
    const float* x  = (const float*)d_in[0];
    // d_in[1] = router_mask (unused by reference)
    const float* We = (const float*)d_in[2];
    const float* be = (const float*)d_in[3];
    const float* Wg = (const float*)d_in[4];
    const float* bg = (const float*)d_in[5];
    float* out = (float*)d_out;

    const int smem_bytes = SMEM_FLOATS * sizeof(float);   // 110,592 B
    cudaFuncSetAttribute(moe_gemm_kernel,
                         cudaFuncAttributeMaxDynamicSharedMemorySize, smem_bytes);

    zero_kernel<<<1, 32>>>();
    prep_kernel<<<2048 + 8192, 256>>>(x, We, Wg, bg);

    dim3 grid(8 /*ntiles*/, 128 /*mtiles max*/, E_EXP);
    moe_gemm_kernel<<<grid, 256, smem_bytes>>>(be, out, 0);  // writes '='
    moe_gemm_kernel<<<grid, 256, smem_bytes>>>(be, out, 1);  // writes '+='
}